// round 12
// baseline (speedup 1.0000x reference)
#include <cuda_runtime.h>
#include <cstdint>
#include <math.h>

// Problem constants (B=4, T=8192, D=2048, E=64, top-k=8)
#define BM 64
#define BN 64
#define BK 32
#define NTHREADS 256

constexpr int M_TOT = 4 * 8192;   // 32768 tokens
constexpr int DDIM  = 2048;
constexpr int NEXP  = 64;
constexpr int TOPK  = 8;

// Relative p-gap below which fp32 GEMM ordering is not provably correct.
// Worst-case two-level accumulation logit error ~2.2e-5 abs -> p-gap error
// <= ~1e-4 * p_max. Flag at 5e-4 * p_max for >=5x margin.
#define FLAG_TAU 5e-4f

// ---------- flagged-token list (device globals: no allocations allowed) ----------
__device__ int g_flag_count;
__device__ int g_flag_list[M_TOT];

// ---------- packed f32x2 helpers (FFMA2 / FADD2: 2 ops per instruction) ----------
__device__ __forceinline__ unsigned long long splat2(float x) {
    unsigned long long r;
    asm("mov.b64 %0, {%1, %1};" : "=l"(r) : "f"(x));
    return r;
}
__device__ __forceinline__ void fma2(unsigned long long& d,
                                     unsigned long long a,
                                     unsigned long long b) {
    asm("fma.rn.f32x2 %0, %1, %2, %0;" : "+l"(d) : "l"(a), "l"(b));
}
__device__ __forceinline__ void add2(unsigned long long& d,
                                     unsigned long long a) {
    asm("add.rn.f32x2 %0, %0, %1;" : "+l"(d) : "l"(a));
}
__device__ __forceinline__ float2 unpack2(unsigned long long v) {
    float2 f;
    asm("mov.b64 {%0, %1}, %2;" : "=f"(f.x), "=f"(f.y) : "l"(v));
    return f;
}

// ---------- shared epilogue: softmax(64) -> iterative stable top-R ----------
// v0 = logit[lane], v1 = logit[lane+32]. Produces wsel/isel (desc by p,
// ties -> lower index first; lax.top_k semantics). Uniform across the warp.
template <int R>
__device__ __forceinline__ void softmax_topk(float v0, float v1, int lane,
                                             float* wsel, int* isel) {
    const float NEG_INF = __int_as_float(0xff800000);
    float mx = fmaxf(v0, v1);
#pragma unroll
    for (int o = 16; o; o >>= 1) mx = fmaxf(mx, __shfl_xor_sync(0xffffffffu, mx, o));
    float e0 = expf(v0 - mx), e1 = expf(v1 - mx);
    float s = e0 + e1;
#pragma unroll
    for (int o = 16; o; o >>= 1) s += __shfl_xor_sync(0xffffffffu, s, o);
    float p0 = __fdiv_rn(e0, s);
    float p1 = __fdiv_rn(e1, s);
#pragma unroll
    for (int r = 0; r < R; r++) {
        float cv; int ci;
        if (p1 > p0) { cv = p1; ci = lane + 32; }
        else         { cv = p0; ci = lane; }
#pragma unroll
        for (int o = 16; o; o >>= 1) {
            float ov = __shfl_xor_sync(0xffffffffu, cv, o);
            int   oi = __shfl_xor_sync(0xffffffffu, ci, o);
            if (ov > cv || (ov == cv && oi < ci)) { cv = ov; ci = oi; }
        }
        wsel[r] = cv; isel[r] = ci;
        if (ci == lane)           p0 = NEG_INF;
        else if (ci == lane + 32) p1 = NEG_INF;
    }
}

// lane0-only: re-softmax over 8 selected weights + store both outputs.
__device__ __forceinline__ void store_token(const float* wsel, const int* isel,
                                            int tg, float* out) {
    float mw = wsel[0];
    float es[TOPK];
    float se = 0.0f;
#pragma unroll
    for (int r = 0; r < TOPK; r++) { es[r] = expf(wsel[r] - mw); se += es[r]; }
    float* ow = out + (size_t)tg * TOPK;
    float* oe = out + (size_t)M_TOT * TOPK + (size_t)tg * TOPK;
#pragma unroll
    for (int r = 0; r < TOPK; r++) {
        ow[r] = __fdiv_rn(es[r], se);
        oe[r] = (float)isel[r];
    }
}

// ---------- kernel 0: reset flag counter (graph-replay determinism) ----------
__global__ void reset_kernel() { g_flag_count = 0; }

// Shared memory: GEMM phase uses As[BK][BM+4] (32*68 = 2176 floats) +
// Bs[BK][BN] (2048 floats) = 4224 floats. Epilogue reuses the SAME floats
// as a logits tile Lg[BM][66] (64*66 = 4224). Exact fit.
#define SMEM_FLOATS 4224
#define AS_STRIDE   68
#define LG_STRIDE   66

// ---------- kernel 1: fast fp32 GEMM + epilogue + knife-edge flagging ----------
__global__ __launch_bounds__(NTHREADS)
void router_kernel(const float* __restrict__ x,
                   const float* __restrict__ w,
                   float* __restrict__ out) {
    __shared__ float smem[SMEM_FLOATS];
    float* As = smem;                       // [BK][BM+4], k-major (transposed x)
    float* Bs = smem + BK * (BM + 4);       // [BK][BN]

    const int tid = threadIdx.x;
    const int m0  = blockIdx.x * BM;
    const int tx  = tid & 15;               // expert group (n)
    const int ty  = tid >> 4;               // token group (m)

    unsigned long long acc[4][2];
#pragma unroll
    for (int i = 0; i < 4; i++) { acc[i][0] = 0ull; acc[i][1] = 0ull; }

    // Two-level accumulation: fresh tile-local accumulator per BK chunk,
    // folded once per tile (keeps worst-case logit error ~2e-5 abs).
    for (int kt = 0; kt < DDIM; kt += BK) {
#pragma unroll
        for (int j = 0; j < 2; j++) {
            int li  = tid + j * NTHREADS;      // 0..511
            int tok = li >> 3;
            int kq  = li & 7;
            float4 v = *(const float4*)(x + (size_t)(m0 + tok) * DDIM + kt + kq * 4);
            As[(kq * 4 + 0) * AS_STRIDE + tok] = v.x;
            As[(kq * 4 + 1) * AS_STRIDE + tok] = v.y;
            As[(kq * 4 + 2) * AS_STRIDE + tok] = v.z;
            As[(kq * 4 + 3) * AS_STRIDE + tok] = v.w;

            int row = li >> 4;
            int c4  = li & 15;
            *(float4*)(Bs + row * BN + c4 * 4) =
                *(const float4*)(w + (size_t)(kt + row) * NEXP + c4 * 4);
        }
        __syncthreads();

        unsigned long long lacc[4][2];
#pragma unroll
        for (int i = 0; i < 4; i++) { lacc[i][0] = 0ull; lacc[i][1] = 0ull; }

#pragma unroll
        for (int kk = 0; kk < BK; kk++) {
            float4 a4 = *(const float4*)(As + kk * AS_STRIDE + ty * 4);
            ulonglong2 bv = *(const ulonglong2*)(Bs + kk * BN + tx * 4);
            unsigned long long a;
            a = splat2(a4.x); fma2(lacc[0][0], a, bv.x); fma2(lacc[0][1], a, bv.y);
            a = splat2(a4.y); fma2(lacc[1][0], a, bv.x); fma2(lacc[1][1], a, bv.y);
            a = splat2(a4.z); fma2(lacc[2][0], a, bv.x); fma2(lacc[2][1], a, bv.y);
            a = splat2(a4.w); fma2(lacc[3][0], a, bv.x); fma2(lacc[3][1], a, bv.y);
        }
#pragma unroll
        for (int i = 0; i < 4; i++) { add2(acc[i][0], lacc[i][0]); add2(acc[i][1], lacc[i][1]); }
        __syncthreads();
    }

    // stash logits tile (reuse smem as Lg[64][66])
#pragma unroll
    for (int i = 0; i < 4; i++) {
        float2 f0 = unpack2(acc[i][0]);
        float2 f1 = unpack2(acc[i][1]);
        float* row = smem + (ty * 4 + i) * LG_STRIDE + tx * 4;
        row[0] = f0.x; row[1] = f0.y; row[2] = f1.x; row[3] = f1.y;
    }
    __syncthreads();

    const int warp = tid >> 5;
    const int lane = tid & 31;

    for (int t8 = 0; t8 < 8; t8++) {
        const int t = warp * 8 + t8;
        float v0 = smem[t * LG_STRIDE + lane];
        float v1 = smem[t * LG_STRIDE + 32 + lane];

        // top-9 so we can check the rank8-vs-rank9 boundary gap too
        float wsel[TOPK + 1];
        int   isel[TOPK + 1];
        softmax_topk<TOPK + 1>(v0, v1, lane, wsel, isel);

        if (lane == 0) {
            const int tg = m0 + t;
            // knife-edge detection: any adjacent gap too small for fp32 proof?
            bool flag = false;
            float tau = wsel[0] * FLAG_TAU;
#pragma unroll
            for (int r = 0; r < TOPK; r++)
                if (wsel[r] - wsel[r + 1] <= tau) flag = true;
            if (flag) {
                int slot = atomicAdd(&g_flag_count, 1);
                g_flag_list[slot] = tg;
            }
            store_token(wsel, isel, tg, out);
        }
    }
}

// ---------- kernel 2: exact (Kahan) recompute for flagged tokens ----------
// 256 threads: 4 threads per expert, each Kahan-sums a 512-k chunk; the 4
// chunk (s,c) pairs are merged in fp64 (error << 0.5 ulp of truth), giving
// the TRUE fp32 logits. Then the identical softmax/top-8 pipeline overwrites
// the token's outputs.
__global__ __launch_bounds__(256)
void exact_fix_kernel(const float* __restrict__ x,
                      const float* __restrict__ w,
                      float* __restrict__ out) {
    __shared__ float sx[DDIM];      // 8 KB: the token's x row
    __shared__ float ss[256], sc[256];
    __shared__ float slog[NEXP];

    const int tid = threadIdx.x;
    const int n = g_flag_count;     // k1 finished (stream order)

    for (int i = blockIdx.x; i < n; i += gridDim.x) {
        const int t = g_flag_list[i];

        for (int j = tid; j < DDIM; j += 256)
            sx[j] = x[(size_t)t * DDIM + j];
        __syncthreads();

        const int e   = tid >> 2;        // expert 0..63
        const int sub = tid & 3;         // k-chunk 0..3
        float s = 0.0f, c = 0.0f;
        const int k0 = sub * (DDIM / 4);
#pragma unroll 8
        for (int k = k0; k < k0 + DDIM / 4; k++) {
            float p = __fmul_rn(sx[k], w[(size_t)k * NEXP + e]);
            float y = __fsub_rn(p, c);
            float tt = __fadd_rn(s, y);
            c = __fsub_rn(__fsub_rn(tt, s), y);
            s = tt;
        }
        ss[tid] = s; sc[tid] = c;
        __syncthreads();

        if (tid < NEXP) {
            double d = 0.0;
#pragma unroll
            for (int q = 0; q < 4; q++)
                d += (double)ss[tid * 4 + q] - (double)sc[tid * 4 + q];
            slog[tid] = (float)d;
        }
        __syncthreads();

        if (tid < 32) {
            float v0 = slog[tid];
            float v1 = slog[tid + 32];
            float wsel[TOPK];
            int   isel[TOPK];
            softmax_topk<TOPK>(v0, v1, tid, wsel, isel);
            if (tid == 0) store_token(wsel, isel, t, out);
        }
        __syncthreads();
    }
}

extern "C" void kernel_launch(void* const* d_in, const int* in_sizes, int n_in,
                              void* d_out, int out_size) {
    const float* x = nullptr;
    const float* w = nullptr;
    for (int i = 0; i < n_in; i++) {
        if (in_sizes[i] == M_TOT * DDIM)      x = (const float*)d_in[i];
        else if (in_sizes[i] == DDIM * NEXP)  w = (const float*)d_in[i];
    }
    float* out = (float*)d_out;
    reset_kernel<<<1, 1>>>();
    router_kernel<<<M_TOT / BM, NTHREADS>>>(x, w, out);
    exact_fix_kernel<<<256, 256>>>(x, w, out);
}

// round 14
// speedup vs baseline: 2.3488x; 2.3488x over previous
#include <cuda_runtime.h>
#include <cuda_bf16.h>
#include <cstdint>
#include <math.h>

// Problem constants (B=4, T=8192, D=2048, E=64, top-k=8)
constexpr int M_TOT = 32768;
constexpr int DDIM  = 2048;
constexpr int NEXP  = 64;
constexpr int TOPK  = 8;

#define CTAM     256            // tokens per CTA
#define KC       32             // k per chunk (bf16 -> 64B rows, SW64)
#define NCHUNK   (DDIM / KC)    // 64
#define RTHREADS 256

// Flag threshold (relative to p_max). bf16 3-product split logit error
// ~1.2e-5 abs -> adjacent-gap uncertainty ~2.4e-5*p_max; 1.5e-4 = 6x margin.
#define FLAG_TAU 1.5e-4f

// ---------------- device globals (no runtime allocation allowed) ----------------
__device__ int g_flag_count;
__device__ int g_flag_list[M_TOT];
// w split into bf16 hi/lo, TRANSPOSED to [n][k] (K-major rows).
__device__ __align__(16) __nv_bfloat16 g_w_hi[NEXP * DDIM];
__device__ __align__(16) __nv_bfloat16 g_w_lo[NEXP * DDIM];

// ---------------- helpers ----------------
__device__ __forceinline__ uint32_t smem_to_u32(const void* p) {
    uint32_t a;
    asm("{ .reg .u64 t; cvta.to.shared.u64 t, %1; cvt.u32.u64 %0, t; }" : "=r"(a) : "l"(p));
    return a;
}
// SW64 swizzle: XOR 16B-unit index (bits[4:6)) with (row>>1)&3 (bits[7:9)).
// Conflict-free for 8-row x 16B ldmatrix reads on 64B-row tiles.
#define SWZ(o) ((o) ^ (((o) >> 3) & 0x30))

__device__ __forceinline__ void ldmatrix_x4(uint32_t* r, uint32_t addr) {
    asm volatile("ldmatrix.sync.aligned.m8n8.x4.shared.b16 {%0,%1,%2,%3}, [%4];"
                 : "=r"(r[0]), "=r"(r[1]), "=r"(r[2]), "=r"(r[3]) : "r"(addr));
}
__device__ __forceinline__ void mma_bf16(float* d, const uint32_t* a,
                                         uint32_t b0, uint32_t b1) {
    asm volatile(
        "mma.sync.aligned.m16n8k16.row.col.f32.bf16.bf16.f32 "
        "{%0,%1,%2,%3}, {%4,%5,%6,%7}, {%8,%9}, {%0,%1,%2,%3};"
        : "+f"(d[0]), "+f"(d[1]), "+f"(d[2]), "+f"(d[3])
        : "r"(a[0]), "r"(a[1]), "r"(a[2]), "r"(a[3]), "r"(b0), "r"(b1));
}
__device__ __forceinline__ void split2(float a, float b, uint32_t& hi, uint32_t& lo) {
    __nv_bfloat16 h0 = __float2bfloat16(a), h1 = __float2bfloat16(b);
    float r0 = a - __bfloat162float(h0), r1 = b - __bfloat162float(h1);
    __nv_bfloat16 l0 = __float2bfloat16(r0), l1 = __float2bfloat16(r1);
    hi = (uint32_t)__bfloat16_as_ushort(h0) | ((uint32_t)__bfloat16_as_ushort(h1) << 16);
    lo = (uint32_t)__bfloat16_as_ushort(l0) | ((uint32_t)__bfloat16_as_ushort(l1) << 16);
}

// ---------------- shared epilogue (proven in round 12) ----------------
template <int R>
__device__ __forceinline__ void softmax_topk(float v0, float v1, int lane,
                                             float* wsel, int* isel) {
    const float NEG_INF = __int_as_float(0xff800000);
    float mx = fmaxf(v0, v1);
#pragma unroll
    for (int o = 16; o; o >>= 1) mx = fmaxf(mx, __shfl_xor_sync(0xffffffffu, mx, o));
    float e0 = expf(v0 - mx), e1 = expf(v1 - mx);
    float s = e0 + e1;
#pragma unroll
    for (int o = 16; o; o >>= 1) s += __shfl_xor_sync(0xffffffffu, s, o);
    float p0 = __fdiv_rn(e0, s);
    float p1 = __fdiv_rn(e1, s);
#pragma unroll
    for (int r = 0; r < R; r++) {
        float cv; int ci;
        if (p1 > p0) { cv = p1; ci = lane + 32; }
        else         { cv = p0; ci = lane; }
#pragma unroll
        for (int o = 16; o; o >>= 1) {
            float ov = __shfl_xor_sync(0xffffffffu, cv, o);
            int   oi = __shfl_xor_sync(0xffffffffu, ci, o);
            if (ov > cv || (ov == cv && oi < ci)) { cv = ov; ci = oi; }
        }
        wsel[r] = cv; isel[r] = ci;
        if (ci == lane)           p0 = NEG_INF;
        else if (ci == lane + 32) p1 = NEG_INF;
    }
}

__device__ __forceinline__ void store_token(const float* wsel, const int* isel,
                                            int tg, float* out) {
    float mw = wsel[0];
    float es[TOPK];
    float se = 0.0f;
#pragma unroll
    for (int r = 0; r < TOPK; r++) { es[r] = expf(wsel[r] - mw); se += es[r]; }
    float* ow = out + (size_t)tg * TOPK;
    float* oe = out + (size_t)M_TOT * TOPK + (size_t)tg * TOPK;
#pragma unroll
    for (int r = 0; r < TOPK; r++) {
        ow[r] = __fdiv_rn(es[r], se);
        oe[r] = (float)isel[r];
    }
}

// ---------------- kernel A: prep — split w into bf16 hi/lo [n][k]; reset flags ----------------
__global__ void prep_w_kernel(const float* __restrict__ w) {
    int i = blockIdx.x * blockDim.x + threadIdx.x;
    if (i == 0) g_flag_count = 0;
    if (i < DDIM * NEXP) {
        int k = i >> 6;          // w is [k][n]
        int n = i & 63;
        float v = w[i];
        __nv_bfloat16 h = __float2bfloat16(v);
        float r = v - __bfloat162float(h);
        g_w_hi[n * DDIM + k] = h;
        g_w_lo[n * DDIM + k] = __float2bfloat16(r);
    }
}

// ---------------- kernel B: HMMA bf16-split router ----------------
// Stage (40960 B): A_hi @0 (16K), A_lo @16384 (16K), B_hi @32768 (4K), B_lo @36864 (4K).
// Two stages = 81920 B. Epilogue reuses [0, 256*66*4) as Lg fp32.
#define STAGE_BYTES 40960
#define ROUTER_SMEM (2 * STAGE_BYTES)
#define LG_STRIDE 66

__global__ __launch_bounds__(RTHREADS)
void router_hmma_kernel(const float* __restrict__ x, float* __restrict__ out) {
    extern __shared__ char dsm[];
    const int tid  = threadIdx.x;
    const int wid  = tid >> 5;
    const int lane = tid & 31;
    const int m0   = blockIdx.x * CTAM;

    const int tok8 = tid >> 3;          // A loader: token = tok8 + j*32? no: s>>3
    const int bn   = tid >> 2;          // B loader: expert row
    const int bcu  = tid & 3;           // B loader: 16B unit

    // accumulators: 2 m-tiles x 8 n-tiles x 4 regs
    float acc[2][8][4];
#pragma unroll
    for (int mt = 0; mt < 2; mt++)
#pragma unroll
        for (int i = 0; i < 8; i++)
#pragma unroll
            for (int q = 0; q < 4; q++) acc[mt][i][q] = 0.0f;

    // ---- prologue: prefetch chunk 0 into registers ----
    float4 xa[8];
    uint4  bhv, blv;
    {
#pragma unroll
        for (int j = 0; j < 8; j++) {
            int s = tid + j * RTHREADS;       // 0..2047
            int tok = s >> 3, kq = s & 7;     // 256 tok x 8 float4
            xa[j] = *(const float4*)(x + (size_t)(m0 + tok) * DDIM + kq * 4);
        }
        bhv = *(const uint4*)((const char*)g_w_hi + (size_t)bn * DDIM * 2 + bcu * 16);
        blv = *(const uint4*)((const char*)g_w_lo + (size_t)bn * DDIM * 2 + bcu * 16);
    }

    const int grp = lane >> 3, r8 = lane & 7;

    for (int c = 0; c < NCHUNK; c++) {
        char* base = dsm + (c & 1) * STAGE_BYTES;

        // ---- STS: split-convert A, copy B (both swizzled) ----
#pragma unroll
        for (int j = 0; j < 8; j++) {
            int s = tid + j * RTHREADS;
            int tok = s >> 3, kq = s & 7;
            uint2 hp, lp;
            split2(xa[j].x, xa[j].y, hp.x, lp.x);
            split2(xa[j].z, xa[j].w, hp.y, lp.y);
            uint32_t off = tok * 64 + kq * 8;
            uint32_t sw  = SWZ(off);
            *(uint2*)(base +         sw) = hp;
            *(uint2*)(base + 16384 + sw) = lp;
        }
        {
            uint32_t off = bn * 64 + bcu * 16;
            uint32_t sw  = SWZ(off);
            *(uint4*)(base + 32768 + sw) = bhv;
            *(uint4*)(base + 36864 + sw) = blv;
        }
        __syncthreads();

        // ---- prefetch chunk c+1 (overlaps with MMA below) ----
        if (c + 1 < NCHUNK) {
#pragma unroll
            for (int j = 0; j < 8; j++) {
                int s = tid + j * RTHREADS;
                int tok = s >> 3, kq = s & 7;
                xa[j] = *(const float4*)(x + (size_t)(m0 + tok) * DDIM
                                           + (c + 1) * KC + kq * 4);
            }
            bhv = *(const uint4*)((const char*)g_w_hi + (size_t)bn * DDIM * 2
                                  + (c + 1) * 64 + bcu * 16);
            blv = *(const uint4*)((const char*)g_w_lo + (size_t)bn * DDIM * 2
                                  + (c + 1) * 64 + bcu * 16);
        }

        // ---- MMA: 2 k16-steps ----
        uint32_t sA = smem_to_u32(base);
        uint32_t sB = sA + 32768;
#pragma unroll
        for (int s = 0; s < 2; s++) {
            uint32_t a_hi[2][4], a_lo[2][4];
#pragma unroll
            for (int mt = 0; mt < 2; mt++) {
                int arow  = wid * 32 + mt * 16 + ((grp & 1) << 3) + r8;
                int aunit = s * 2 + (grp >> 1);
                uint32_t aoff = SWZ((uint32_t)(arow * 64 + aunit * 16));
                ldmatrix_x4(a_hi[mt], sA + aoff);
                ldmatrix_x4(a_lo[mt], sA + 16384 + aoff);
            }
#pragma unroll
            for (int i = 0; i < 4; i++) {          // n-tile pairs (2i, 2i+1)
                int brow  = i * 16 + ((grp >> 1) << 3) + r8;
                int bunit = s * 2 + (grp & 1);
                uint32_t boff = SWZ((uint32_t)(brow * 64 + bunit * 16));
                uint32_t bh[4], bl[4];
                ldmatrix_x4(bh, sB + boff);
                ldmatrix_x4(bl, sB + 4096 + boff);
#pragma unroll
                for (int mt = 0; mt < 2; mt++) {
                    mma_bf16(acc[mt][2 * i],     a_hi[mt], bh[0], bh[1]);
                    mma_bf16(acc[mt][2 * i],     a_lo[mt], bh[0], bh[1]);
                    mma_bf16(acc[mt][2 * i],     a_hi[mt], bl[0], bl[1]);
                    mma_bf16(acc[mt][2 * i + 1], a_hi[mt], bh[2], bh[3]);
                    mma_bf16(acc[mt][2 * i + 1], a_lo[mt], bh[2], bh[3]);
                    mma_bf16(acc[mt][2 * i + 1], a_hi[mt], bl[2], bl[3]);
                }
            }
        }
        // single barrier per iter: next STS targets the other stage; the
        // stage written at c+2 was last read at c, separated by sync(c+1).
    }

    // ---- fragments -> Lg[256][66] fp32 ----
    __syncthreads();
    float* Lg = (float*)dsm;
#pragma unroll
    for (int mt = 0; mt < 2; mt++) {
        int r = wid * 32 + mt * 16 + (lane >> 2);
        int cb = (lane & 3) * 2;
#pragma unroll
        for (int i = 0; i < 8; i++) {
            *(float2*)&Lg[r * LG_STRIDE + i * 8 + cb] =
                make_float2(acc[mt][i][0], acc[mt][i][1]);
            *(float2*)&Lg[(r + 8) * LG_STRIDE + i * 8 + cb] =
                make_float2(acc[mt][i][2], acc[mt][i][3]);
        }
    }
    __syncthreads();

    // ---- softmax(64) -> top-9 -> flag -> softmax(8) -> store ----
    for (int tt = 0; tt < 32; tt++) {
        const int t = wid * 32 + tt;
        float v0 = Lg[t * LG_STRIDE + lane];
        float v1 = Lg[t * LG_STRIDE + 32 + lane];
        float wsel[TOPK + 1];
        int   isel[TOPK + 1];
        softmax_topk<TOPK + 1>(v0, v1, lane, wsel, isel);
        if (lane == 0) {
            const int tg = m0 + t;
            bool flag = false;
            float tau = wsel[0] * FLAG_TAU;
#pragma unroll
            for (int r = 0; r < TOPK; r++)
                if (wsel[r] - wsel[r + 1] <= tau) flag = true;
            if (flag) {
                int slot = atomicAdd(&g_flag_count, 1);
                g_flag_list[slot] = tg;
            }
            store_token(wsel, isel, tg, out);
        }
    }
}

// ---------------- kernel C: exact (Kahan) recompute of flagged tokens ----------------
__global__ __launch_bounds__(256)
void exact_fix_kernel(const float* __restrict__ x,
                      const float* __restrict__ w,
                      float* __restrict__ out) {
    __shared__ float sx[DDIM];
    __shared__ float ss[256], sc[256];
    __shared__ float slog[NEXP];

    const int tid = threadIdx.x;
    const int n = g_flag_count;

    for (int i = blockIdx.x; i < n; i += gridDim.x) {
        const int t = g_flag_list[i];
        for (int j = tid; j < DDIM; j += 256)
            sx[j] = x[(size_t)t * DDIM + j];
        __syncthreads();

        const int e   = tid >> 2;
        const int sub = tid & 3;
        float s = 0.0f, c = 0.0f;
        const int k0 = sub * (DDIM / 4);
#pragma unroll 8
        for (int k = k0; k < k0 + DDIM / 4; k++) {
            float p = __fmul_rn(sx[k], w[(size_t)k * NEXP + e]);
            float y = __fsub_rn(p, c);
            float tt = __fadd_rn(s, y);
            c = __fsub_rn(__fsub_rn(tt, s), y);
            s = tt;
        }
        ss[tid] = s; sc[tid] = c;
        __syncthreads();

        if (tid < NEXP) {
            double d = 0.0;
#pragma unroll
            for (int q = 0; q < 4; q++)
                d += (double)ss[tid * 4 + q] - (double)sc[tid * 4 + q];
            slog[tid] = (float)d;
        }
        __syncthreads();

        if (tid < 32) {
            float v0 = slog[tid];
            float v1 = slog[tid + 32];
            float wsel[TOPK];
            int   isel[TOPK];
            softmax_topk<TOPK>(v0, v1, tid, wsel, isel);
            if (tid == 0) store_token(wsel, isel, t, out);
        }
        __syncthreads();
    }
}

extern "C" void kernel_launch(void* const* d_in, const int* in_sizes, int n_in,
                              void* d_out, int out_size) {
    const float* x = nullptr;
    const float* w = nullptr;
    for (int i = 0; i < n_in; i++) {
        if (in_sizes[i] == M_TOT * DDIM)      x = (const float*)d_in[i];
        else if (in_sizes[i] == DDIM * NEXP)  w = (const float*)d_in[i];
    }
    float* out = (float*)d_out;

    cudaFuncSetAttribute(router_hmma_kernel,
                         cudaFuncAttributeMaxDynamicSharedMemorySize, ROUTER_SMEM);

    prep_w_kernel<<<(DDIM * NEXP + 255) / 256, 256>>>(w);
    router_hmma_kernel<<<M_TOT / CTAM, RTHREADS, ROUTER_SMEM>>>(x, out);
    exact_fix_kernel<<<2048, 256>>>(x, w, out);
}

// round 15
// speedup vs baseline: 2.7574x; 1.1740x over previous
#include <cuda_runtime.h>
#include <cuda_bf16.h>
#include <cstdint>
#include <math.h>

// Problem constants (B=4, T=8192, D=2048, E=64, top-k=8)
constexpr int M_TOT = 32768;
constexpr int DDIM  = 2048;
constexpr int NEXP  = 64;
constexpr int TOPK  = 8;

#define CTAM     128            // tokens per CTA (halved: 2 CTAs/SM)
#define KC       32             // k per chunk (bf16 -> 64B rows, SW64)
#define NCHUNK   (DDIM / KC)    // 64
#define RTHREADS 256

// Flag threshold (relative to p_max). bf16 3-product split logit error
// ~1.2e-5 abs -> adjacent-gap uncertainty ~2.4e-5*p_max; 1.5e-4 = 6x margin.
#define FLAG_TAU 1.5e-4f

// ---------------- device globals (no runtime allocation allowed) ----------------
__device__ int g_flag_count;
__device__ int g_flag_list[M_TOT];
// w split into bf16 hi/lo, TRANSPOSED to [n][k] (K-major rows).
__device__ __align__(16) __nv_bfloat16 g_w_hi[NEXP * DDIM];
__device__ __align__(16) __nv_bfloat16 g_w_lo[NEXP * DDIM];

// ---------------- helpers ----------------
__device__ __forceinline__ uint32_t smem_to_u32(const void* p) {
    uint32_t a;
    asm("{ .reg .u64 t; cvta.to.shared.u64 t, %1; cvt.u32.u64 %0, t; }" : "=r"(a) : "l"(p));
    return a;
}
// SW64 swizzle: XOR 16B-unit index (bits[4:6)) with (row>>1)&3 (bits[7:9)).
// Conflict-free for 8-row x 16B ldmatrix reads on 64B-row tiles.
#define SWZ(o) ((o) ^ (((o) >> 3) & 0x30))

__device__ __forceinline__ void ldmatrix_x4(uint32_t* r, uint32_t addr) {
    asm volatile("ldmatrix.sync.aligned.m8n8.x4.shared.b16 {%0,%1,%2,%3}, [%4];"
                 : "=r"(r[0]), "=r"(r[1]), "=r"(r[2]), "=r"(r[3]) : "r"(addr));
}
__device__ __forceinline__ void mma_bf16(float* d, const uint32_t* a,
                                         uint32_t b0, uint32_t b1) {
    asm volatile(
        "mma.sync.aligned.m16n8k16.row.col.f32.bf16.bf16.f32 "
        "{%0,%1,%2,%3}, {%4,%5,%6,%7}, {%8,%9}, {%0,%1,%2,%3};"
        : "+f"(d[0]), "+f"(d[1]), "+f"(d[2]), "+f"(d[3])
        : "r"(a[0]), "r"(a[1]), "r"(a[2]), "r"(a[3]), "r"(b0), "r"(b1));
}
__device__ __forceinline__ void split2(float a, float b, uint32_t& hi, uint32_t& lo) {
    __nv_bfloat16 h0 = __float2bfloat16(a), h1 = __float2bfloat16(b);
    float r0 = a - __bfloat162float(h0), r1 = b - __bfloat162float(h1);
    __nv_bfloat16 l0 = __float2bfloat16(r0), l1 = __float2bfloat16(r1);
    hi = (uint32_t)__bfloat16_as_ushort(h0) | ((uint32_t)__bfloat16_as_ushort(h1) << 16);
    lo = (uint32_t)__bfloat16_as_ushort(l0) | ((uint32_t)__bfloat16_as_ushort(l1) << 16);
}

// ---------------- shared epilogue (proven rounds 12/14) ----------------
template <int R>
__device__ __forceinline__ void softmax_topk(float v0, float v1, int lane,
                                             float* wsel, int* isel) {
    const float NEG_INF = __int_as_float(0xff800000);
    float mx = fmaxf(v0, v1);
#pragma unroll
    for (int o = 16; o; o >>= 1) mx = fmaxf(mx, __shfl_xor_sync(0xffffffffu, mx, o));
    float e0 = expf(v0 - mx), e1 = expf(v1 - mx);
    float s = e0 + e1;
#pragma unroll
    for (int o = 16; o; o >>= 1) s += __shfl_xor_sync(0xffffffffu, s, o);
    float p0 = __fdiv_rn(e0, s);
    float p1 = __fdiv_rn(e1, s);
#pragma unroll
    for (int r = 0; r < R; r++) {
        float cv; int ci;
        if (p1 > p0) { cv = p1; ci = lane + 32; }
        else         { cv = p0; ci = lane; }
#pragma unroll
        for (int o = 16; o; o >>= 1) {
            float ov = __shfl_xor_sync(0xffffffffu, cv, o);
            int   oi = __shfl_xor_sync(0xffffffffu, ci, o);
            if (ov > cv || (ov == cv && oi < ci)) { cv = ov; ci = oi; }
        }
        wsel[r] = cv; isel[r] = ci;
        if (ci == lane)           p0 = NEG_INF;
        else if (ci == lane + 32) p1 = NEG_INF;
    }
}

__device__ __forceinline__ void store_token(const float* wsel, const int* isel,
                                            int tg, float* out) {
    float mw = wsel[0];
    float es[TOPK];
    float se = 0.0f;
#pragma unroll
    for (int r = 0; r < TOPK; r++) { es[r] = expf(wsel[r] - mw); se += es[r]; }
    float* ow = out + (size_t)tg * TOPK;
    float* oe = out + (size_t)M_TOT * TOPK + (size_t)tg * TOPK;
#pragma unroll
    for (int r = 0; r < TOPK; r++) {
        ow[r] = __fdiv_rn(es[r], se);
        oe[r] = (float)isel[r];
    }
}

// ---------------- kernel A: prep — split w into bf16 hi/lo [n][k]; reset flags ----------------
__global__ void prep_w_kernel(const float* __restrict__ w) {
    int i = blockIdx.x * blockDim.x + threadIdx.x;
    if (i == 0) g_flag_count = 0;
    if (i < DDIM * NEXP) {
        int k = i >> 6;          // w is [k][n]
        int n = i & 63;
        float v = w[i];
        __nv_bfloat16 h = __float2bfloat16(v);
        float r = v - __bfloat162float(h);
        g_w_hi[n * DDIM + k] = h;
        g_w_lo[n * DDIM + k] = __float2bfloat16(r);
    }
}

// ---------------- kernel B: HMMA bf16-split router (2 CTAs/SM) ----------------
// Stage (24576 B): A_hi @0 (8K), A_lo @8192 (8K), B_hi @16384 (4K), B_lo @20480 (4K).
// Two stages = 49152 B. Epilogue reuses [0, 128*66*4 = 33792) as Lg fp32.
#define STAGE_BYTES 24576
#define ROUTER_SMEM (2 * STAGE_BYTES)
#define LG_STRIDE 66

__global__ __launch_bounds__(RTHREADS, 2)
void router_hmma_kernel(const float* __restrict__ x, float* __restrict__ out) {
    extern __shared__ char dsm[];
    const int tid  = threadIdx.x;
    const int wid  = tid >> 5;
    const int lane = tid & 31;
    const int m0   = blockIdx.x * CTAM;

    const int bn   = tid >> 2;          // B loader: expert row (0..63)
    const int bcu  = tid & 3;           // B loader: 16B unit (0..3)

    // accumulators: 1 m-tile x 8 n-tiles x 4 regs
    float acc[8][4];
#pragma unroll
    for (int i = 0; i < 8; i++)
#pragma unroll
        for (int q = 0; q < 4; q++) acc[i][q] = 0.0f;

    // ---- prologue: prefetch chunk 0 into registers ----
    float4 xa[4];
    uint4  bhv, blv;
#pragma unroll
    for (int j = 0; j < 4; j++) {
        int s = tid + j * RTHREADS;       // 0..1023
        int tok = s >> 3, kq = s & 7;     // 128 tok x 8 float4
        xa[j] = *(const float4*)(x + (size_t)(m0 + tok) * DDIM + kq * 4);
    }
    bhv = *(const uint4*)((const char*)g_w_hi + (size_t)bn * DDIM * 2 + bcu * 16);
    blv = *(const uint4*)((const char*)g_w_lo + (size_t)bn * DDIM * 2 + bcu * 16);

    const int grp = lane >> 3, r8 = lane & 7;

    for (int c = 0; c < NCHUNK; c++) {
        char* base = dsm + (c & 1) * STAGE_BYTES;

        // ---- STS: split-convert A, copy B (both swizzled) ----
#pragma unroll
        for (int j = 0; j < 4; j++) {
            int s = tid + j * RTHREADS;
            int tok = s >> 3, kq = s & 7;
            uint2 hp, lp;
            split2(xa[j].x, xa[j].y, hp.x, lp.x);
            split2(xa[j].z, xa[j].w, hp.y, lp.y);
            uint32_t off = tok * 64 + kq * 8;
            uint32_t sw  = SWZ(off);
            *(uint2*)(base +        sw) = hp;
            *(uint2*)(base + 8192 + sw) = lp;
        }
        {
            uint32_t off = bn * 64 + bcu * 16;
            uint32_t sw  = SWZ(off);
            *(uint4*)(base + 16384 + sw) = bhv;
            *(uint4*)(base + 20480 + sw) = blv;
        }
        __syncthreads();

        // ---- prefetch chunk c+1 (overlaps with MMA below) ----
        if (c + 1 < NCHUNK) {
#pragma unroll
            for (int j = 0; j < 4; j++) {
                int s = tid + j * RTHREADS;
                int tok = s >> 3, kq = s & 7;
                xa[j] = *(const float4*)(x + (size_t)(m0 + tok) * DDIM
                                           + (c + 1) * KC + kq * 4);
            }
            bhv = *(const uint4*)((const char*)g_w_hi + (size_t)bn * DDIM * 2
                                  + (c + 1) * 64 + bcu * 16);
            blv = *(const uint4*)((const char*)g_w_lo + (size_t)bn * DDIM * 2
                                  + (c + 1) * 64 + bcu * 16);
        }

        // ---- MMA: 2 k16-steps ----
        uint32_t sA = smem_to_u32(base);
        uint32_t sB = sA + 16384;
#pragma unroll
        for (int s = 0; s < 2; s++) {
            uint32_t a_hi[4], a_lo[4];
            {
                int arow  = wid * 16 + ((grp & 1) << 3) + r8;
                int aunit = s * 2 + (grp >> 1);
                uint32_t aoff = SWZ((uint32_t)(arow * 64 + aunit * 16));
                ldmatrix_x4(a_hi, sA + aoff);
                ldmatrix_x4(a_lo, sA + 8192 + aoff);
            }
#pragma unroll
            for (int i = 0; i < 4; i++) {          // n-tile pairs (2i, 2i+1)
                int brow  = i * 16 + ((grp >> 1) << 3) + r8;
                int bunit = s * 2 + (grp & 1);
                uint32_t boff = SWZ((uint32_t)(brow * 64 + bunit * 16));
                uint32_t bh[4], bl[4];
                ldmatrix_x4(bh, sB + boff);
                ldmatrix_x4(bl, sB + 4096 + boff);
                mma_bf16(acc[2 * i],     a_hi, bh[0], bh[1]);
                mma_bf16(acc[2 * i],     a_lo, bh[0], bh[1]);
                mma_bf16(acc[2 * i],     a_hi, bl[0], bl[1]);
                mma_bf16(acc[2 * i + 1], a_hi, bh[2], bh[3]);
                mma_bf16(acc[2 * i + 1], a_lo, bh[2], bh[3]);
                mma_bf16(acc[2 * i + 1], a_hi, bl[2], bl[3]);
            }
        }
        // single barrier per iter: stage written at c+2 was last read at c,
        // separated by sync(c+1) which all warps pass only after MMA(c).
    }

    // ---- fragments -> Lg[128][66] fp32 ----
    __syncthreads();
    float* Lg = (float*)dsm;
    {
        int r  = wid * 16 + (lane >> 2);
        int cb = (lane & 3) * 2;
#pragma unroll
        for (int i = 0; i < 8; i++) {
            *(float2*)&Lg[r * LG_STRIDE + i * 8 + cb] =
                make_float2(acc[i][0], acc[i][1]);
            *(float2*)&Lg[(r + 8) * LG_STRIDE + i * 8 + cb] =
                make_float2(acc[i][2], acc[i][3]);
        }
    }
    __syncthreads();

    // ---- softmax(64) -> top-9 -> flag -> softmax(8) -> store ----
    for (int tt = 0; tt < 16; tt++) {
        const int t = wid * 16 + tt;
        float v0 = Lg[t * LG_STRIDE + lane];
        float v1 = Lg[t * LG_STRIDE + 32 + lane];
        float wsel[TOPK + 1];
        int   isel[TOPK + 1];
        softmax_topk<TOPK + 1>(v0, v1, lane, wsel, isel);
        if (lane == 0) {
            const int tg = m0 + t;
            bool flag = false;
            float tau = wsel[0] * FLAG_TAU;
#pragma unroll
            for (int r = 0; r < TOPK; r++)
                if (wsel[r] - wsel[r + 1] <= tau) flag = true;
            if (flag) {
                int slot = atomicAdd(&g_flag_count, 1);
                g_flag_list[slot] = tg;
            }
            store_token(wsel, isel, tg, out);
        }
    }
}

// ---------------- kernel C: exact (Kahan) recompute of flagged tokens ----------------
__global__ __launch_bounds__(256)
void exact_fix_kernel(const float* __restrict__ x,
                      const float* __restrict__ w,
                      float* __restrict__ out) {
    __shared__ float sx[DDIM];
    __shared__ float ss[256], sc[256];
    __shared__ float slog[NEXP];

    const int tid = threadIdx.x;
    const int n = g_flag_count;

    for (int i = blockIdx.x; i < n; i += gridDim.x) {
        const int t = g_flag_list[i];
        for (int j = tid; j < DDIM; j += 256)
            sx[j] = x[(size_t)t * DDIM + j];
        __syncthreads();

        const int e   = tid >> 2;
        const int sub = tid & 3;
        float s = 0.0f, c = 0.0f;
        const int k0 = sub * (DDIM / 4);
#pragma unroll 8
        for (int k = k0; k < k0 + DDIM / 4; k++) {
            float p = __fmul_rn(sx[k], w[(size_t)k * NEXP + e]);
            float y = __fsub_rn(p, c);
            float tt = __fadd_rn(s, y);
            c = __fsub_rn(__fsub_rn(tt, s), y);
            s = tt;
        }
        ss[tid] = s; sc[tid] = c;
        __syncthreads();

        if (tid < NEXP) {
            double d = 0.0;
#pragma unroll
            for (int q = 0; q < 4; q++)
                d += (double)ss[tid * 4 + q] - (double)sc[tid * 4 + q];
            slog[tid] = (float)d;
        }
        __syncthreads();

        if (tid < 32) {
            float v0 = slog[tid];
            float v1 = slog[tid + 32];
            float wsel[TOPK];
            int   isel[TOPK];
            softmax_topk<TOPK>(v0, v1, tid, wsel, isel);
            if (tid == 0) store_token(wsel, isel, t, out);
        }
        __syncthreads();
    }
}

extern "C" void kernel_launch(void* const* d_in, const int* in_sizes, int n_in,
                              void* d_out, int out_size) {
    const float* x = nullptr;
    const float* w = nullptr;
    for (int i = 0; i < n_in; i++) {
        if (in_sizes[i] == M_TOT * DDIM)      x = (const float*)d_in[i];
        else if (in_sizes[i] == DDIM * NEXP)  w = (const float*)d_in[i];
    }
    float* out = (float*)d_out;

    cudaFuncSetAttribute(router_hmma_kernel,
                         cudaFuncAttributeMaxDynamicSharedMemorySize, ROUTER_SMEM);

    prep_w_kernel<<<(DDIM * NEXP + 255) / 256, 256>>>(w);
    router_hmma_kernel<<<M_TOT / CTAM, RTHREADS, ROUTER_SMEM>>>(x, out);
    exact_fix_kernel<<<2048, 256>>>(x, w, out);
}